// round 16
// baseline (speedup 1.0000x reference)
#include <cuda_runtime.h>
#include <cuda_fp16.h>
#include <cstdint>

#define BATCH 8
#define NSEQ  2048
#define DIM   512
#define ROWS  (BATCH * NSEQ)   // 16384

// ---- mma.sync GEMM tiling ----
#define BM 128
#define BK 64
#define NTHREADS 128
#define ROWB 144                        // smem row stride (bytes): 128+16, conflict-free
#define A_SM (BM * ROWB)                // 18432
#define NSTAGE 3

#define XSZ (ROWS * DIM)
#define WSZ (DIM * DIM)
#define SSZ ((size_t)BATCH * NSEQ * NSEQ)

// ---------------------------------------------------------------------------
// Scratch (allocation-free rule: __device__ globals)
// ---------------------------------------------------------------------------
__device__ __half g_xh[2][XSZ];
__device__ __half g_wqh[2][WSZ];
__device__ __half g_wkh[2][WSZ];
__device__ __half g_wvh[2][WSZ];
__device__ __half g_qh[2][XSZ];
__device__ __half g_kh[2][XSZ];
__device__ __half g_vth[2][(size_t)BATCH * DIM * NSEQ];
__device__ float  g_s[SSZ];
__device__ __half g_ph[2][SSZ];

// ---------------------------------------------------------------------------
// PTX helpers
// ---------------------------------------------------------------------------
static __device__ __forceinline__ uint32_t smem_u32(const void* p) {
    uint32_t a;
    asm("{ .reg .u64 t; cvta.to.shared.u64 t, %1; cvt.u32.u64 %0, t; }" : "=r"(a) : "l"(p));
    return a;
}
static __device__ __forceinline__ void cp16(uint32_t saddr, const void* g) {
    asm volatile("cp.async.cg.shared.global [%0], [%1], 16;" :: "r"(saddr), "l"(g));
}
static __device__ __forceinline__ void cp_commit() {
    asm volatile("cp.async.commit_group;" ::: "memory");
}
static __device__ __forceinline__ void cp_wait0() {
    asm volatile("cp.async.wait_group 0;" ::: "memory");
}
static __device__ __forceinline__ void cp_wait1() {
    asm volatile("cp.async.wait_group 1;" ::: "memory");
}
#define LDSM4(R0, R1, R2, R3, addr) \
    asm volatile("ldmatrix.sync.aligned.m8n8.x4.shared.b16 {%0,%1,%2,%3}, [%4];" \
                 : "=r"(R0), "=r"(R1), "=r"(R2), "=r"(R3) : "r"(addr))
#define MMA16816(c0, c1, c2, c3, a0, a1, a2, a3, b0, b1) \
    asm volatile("mma.sync.aligned.m16n8k16.row.col.f32.f16.f16.f32 " \
                 "{%0,%1,%2,%3}, {%4,%5,%6,%7}, {%8,%9}, {%0,%1,%2,%3};" \
                 : "+f"(c0), "+f"(c1), "+f"(c2), "+f"(c3) \
                 : "r"(a0), "r"(a1), "r"(a2), "r"(a3), "r"(b0), "r"(b1))

// ---------------------------------------------------------------------------
// Elementwise 2-way fp16 splits
// ---------------------------------------------------------------------------
static __device__ __forceinline__ void split2_body(const float* in, __half* o1,
                                                   __half* o2, int i)
{
    float4 v = ((const float4*)in)[i];
    float val[4] = {v.x, v.y, v.z, v.w};
    __half h1[4], h2[4];
#pragma unroll
    for (int j = 0; j < 4; j++) {
        h1[j] = __float2half_rn(val[j]);
        h2[j] = __float2half_rn(val[j] - __half2float(h1[j]));
    }
    ((__half2*)o1)[2 * i]     = __halves2half2(h1[0], h1[1]);
    ((__half2*)o1)[2 * i + 1] = __halves2half2(h1[2], h1[3]);
    ((__half2*)o2)[2 * i]     = __halves2half2(h2[0], h2[1]);
    ((__half2*)o2)[2 * i + 1] = __halves2half2(h2[2], h2[3]);
}

__global__ void split2_kernel(const float* __restrict__ in,
                              __half* __restrict__ o1,
                              __half* __restrict__ o2, int n4)
{
    int i = blockIdx.x * blockDim.x + threadIdx.x;
    if (i < n4) split2_body(in, o1, o2, i);
}

// one launch for the three weight matrices (blockIdx.y selects)
__global__ void wsplit2_kernel(const float* __restrict__ Wq,
                               const float* __restrict__ Wk,
                               const float* __restrict__ Wv,
                               __half* __restrict__ q1, __half* __restrict__ q2,
                               __half* __restrict__ k1, __half* __restrict__ k2,
                               __half* __restrict__ v1, __half* __restrict__ v2,
                               int n4)
{
    int i = blockIdx.x * blockDim.x + threadIdx.x;
    if (i >= n4) return;
    if (blockIdx.y == 0)      split2_body(Wq, q1, q2, i);
    else if (blockIdx.y == 1) split2_body(Wk, k1, k2, i);
    else                      split2_body(Wv, v1, v2, i);
}

// ---------------------------------------------------------------------------
// Softmax over rows of S; writes 2-way fp16 split P
// ---------------------------------------------------------------------------
__global__ __launch_bounds__(256) void softmax_kernel()
{
    __shared__ float red[8];
    const float* S = g_s + (size_t)blockIdx.x * NSEQ;
    const int tid = threadIdx.x, lane = tid & 31, wid = tid >> 5;

    float4 v0 = *(const float4*)(S + tid * 8);
    float4 v1 = *(const float4*)(S + tid * 8 + 4);
    float e[8] = {v0.x, v0.y, v0.z, v0.w, v1.x, v1.y, v1.z, v1.w};

    float m = e[0];
#pragma unroll
    for (int i = 1; i < 8; i++) m = fmaxf(m, e[i]);
#pragma unroll
    for (int off = 16; off > 0; off >>= 1) m = fmaxf(m, __shfl_xor_sync(~0u, m, off));
    if (lane == 0) red[wid] = m;
    __syncthreads();
    float bm = red[0];
#pragma unroll
    for (int i = 1; i < 8; i++) bm = fmaxf(bm, red[i]);
    __syncthreads();

    float s = 0.f;
#pragma unroll
    for (int i = 0; i < 8; i++) { e[i] = __expf(e[i] - bm); s += e[i]; }
#pragma unroll
    for (int off = 16; off > 0; off >>= 1) s += __shfl_xor_sync(~0u, s, off);
    if (lane == 0) red[wid] = s;
    __syncthreads();
    float bs = 0.f;
#pragma unroll
    for (int i = 0; i < 8; i++) bs += red[i];
    float inv = 1.0f / bs;

    size_t base = (size_t)blockIdx.x * NSEQ + tid * 8;
    __half h1[8], h2[8];
#pragma unroll
    for (int i = 0; i < 8; i++) {
        float p = e[i] * inv;
        h1[i] = __float2half_rn(p);
        h2[i] = __float2half_rn(p - __half2float(h1[i]));
    }
#pragma unroll
    for (int i = 0; i < 4; i++) {
        ((__half2*)(g_ph[0] + base))[i] = __halves2half2(h1[2 * i], h1[2 * i + 1]);
        ((__half2*)(g_ph[1] + base))[i] = __halves2half2(h2[2 * i], h2[2 * i + 1]);
    }
}

// ---------------------------------------------------------------------------
// GEMM core: C[m,n] = sum_p sum_k A_p[m,k]*B_p[n,k] (+bias[n])
// MODE 0: fp32 out.  MODE 2: 2-way fp16 split out (row-major).
// MODE 3: 2-way fp16 split out, TRANSPOSED to [b][e][m] (for V).
// BNT: block n-tile (128 or 64). 128 threads; warp grid 2(m) x 2(n).
// ---------------------------------------------------------------------------
template <int MODE, int BNT>
static __device__ __forceinline__ void gemm_core(
    const __half* const* Aps, const __half* const* Bps,
    long long batchA, long long batchB, long long batchC,
    int npairs, int K, int lda, int ldb, int ldc,
    float* Cf, __half* C1, __half* C2, const float* bias,
    int nt, int mt, int bz, char* smem)
{
    constexpr int B_SMT    = BNT * ROWB;
    constexpr int STAGE_T  = A_SM + B_SMT;
    constexpr int NJ       = BNT / 16;       // n8-tiles per warp

    const int tid  = threadIdx.x;
    const int wid  = tid >> 5;
    const int lane = tid & 31;

    const int m_base = (wid & 1) * 64;
    const int n_base = (wid >> 1) * (BNT / 2);

    const uint32_t s0 = smem_u32(smem);

    const int KCH = K / BK;
    const int NIT = npairs * KCH;

    float acc[4][NJ][4];
#pragma unroll
    for (int i = 0; i < 4; i++)
#pragma unroll
        for (int j = 0; j < NJ; j++)
#pragma unroll
            for (int r = 0; r < 4; r++) acc[i][j][r] = 0.f;

    const int lrow0 = tid >> 3;          // 0..15
    const int lc16  = tid & 7;           // 16B chunk within 128B row

    auto load_stage = [&](int it, int s) {
        int p = it / KCH, k0 = (it % KCH) * BK;
        const __half* Ab = Aps[p] + (size_t)bz * batchA + k0;
        const __half* Bb = Bps[p] + (size_t)bz * batchB + k0;
        uint32_t dA = s0 + s * STAGE_T;
        uint32_t dB = dA + A_SM;
#pragma unroll
        for (int h = 0; h < BM / 16; h++) {
            int r = lrow0 + h * 16;
            cp16(dA + r * ROWB + lc16 * 16,
                 Ab + (size_t)(mt * BM + r) * lda + lc16 * 8);
        }
#pragma unroll
        for (int h = 0; h < BNT / 16; h++) {
            int r = lrow0 + h * 16;
            cp16(dB + r * ROWB + lc16 * 16,
                 Bb + (size_t)(nt * BNT + r) * ldb + lc16 * 8);
        }
        cp_commit();
    };

    load_stage(0, 0);
    if (NIT > 1) load_stage(1, 1);

    int st = 0;
    for (int it = 0; it < NIT; it++) {
        if (it + 1 < NIT) cp_wait1(); else cp_wait0();
        __syncthreads();
        if (it + 2 < NIT) {
            int s2 = st + 2; if (s2 >= NSTAGE) s2 -= NSTAGE;
            load_stage(it + 2, s2);
        }

        uint32_t bA = s0 + st * STAGE_T;
        uint32_t bB = bA + A_SM;
#pragma unroll
        for (int ks = 0; ks < 4; ks++) {
            uint32_t a[4][4];
#pragma unroll
            for (int mi = 0; mi < 4; mi++) {
                int row = m_base + mi * 16 + (lane & 15);
                int kc  = ks * 16 + (lane >> 4) * 8;
                LDSM4(a[mi][0], a[mi][1], a[mi][2], a[mi][3],
                      bA + row * ROWB + kc * 2);
            }
            uint32_t b[NJ][2];
#pragma unroll
            for (int j2 = 0; j2 < NJ / 2; j2++) {
                int grp = lane >> 3;
                int row = n_base + j2 * 16 + ((grp >> 1) * 8) + (lane & 7);
                int kc  = ks * 16 + (grp & 1) * 8;
                uint32_t r0, r1, r2, r3;
                LDSM4(r0, r1, r2, r3, bB + row * ROWB + kc * 2);
                b[2 * j2][0] = r0; b[2 * j2][1] = r1;
                b[2 * j2 + 1][0] = r2; b[2 * j2 + 1][1] = r3;
            }
#pragma unroll
            for (int mi = 0; mi < 4; mi++)
#pragma unroll
                for (int nj = 0; nj < NJ; nj++)
                    MMA16816(acc[mi][nj][0], acc[mi][nj][1], acc[mi][nj][2], acc[mi][nj][3],
                             a[mi][0], a[mi][1], a[mi][2], a[mi][3],
                             b[nj][0], b[nj][1]);
        }
        if (++st >= NSTAGE) st = 0;
    }

    const int r0l = lane >> 2;
    const int c0l = (lane & 3) * 2;
#pragma unroll
    for (int mi = 0; mi < 4; mi++) {
#pragma unroll
        for (int half = 0; half < 2; half++) {
            int grow = mt * BM + m_base + mi * 16 + r0l + half * 8;
#pragma unroll
            for (int nj = 0; nj < NJ; nj++) {
                int gcol = nt * BNT + n_base + nj * 8 + c0l;
                float v0 = acc[mi][nj][2 * half];
                float v1 = acc[mi][nj][2 * half + 1];
                if (bias) { v0 += bias[gcol]; v1 += bias[gcol + 1]; }
                if (MODE == 0) {
                    float* C = Cf + (size_t)bz * batchC + (size_t)grow * ldc + gcol;
                    *(float2*)C = make_float2(v0, v1);
                } else if (MODE == 2) {
                    size_t off = (size_t)grow * ldc + gcol;
                    __half a1 = __float2half_rn(v0);
                    __half a2 = __float2half_rn(v0 - __half2float(a1));
                    __half b1 = __float2half_rn(v1);
                    __half b2 = __float2half_rn(v1 - __half2float(b1));
                    *(__half2*)(C1 + off) = __halves2half2(a1, b1);
                    *(__half2*)(C2 + off) = __halves2half2(a2, b2);
                } else {
                    // transposed: vth[b][e][m]; b = grow/NSEQ, m = grow%NSEQ, e = gcol
                    size_t idx = ((size_t)(grow >> 11) * DIM + gcol) * NSEQ + (grow & (NSEQ - 1));
                    __half a1 = __float2half_rn(v0);
                    __half a2 = __float2half_rn(v0 - __half2float(a1));
                    __half b1 = __float2half_rn(v1);
                    __half b2 = __float2half_rn(v1 - __half2float(b1));
                    C1[idx] = a1;        C2[idx] = a2;         // e = gcol
                    C1[idx + NSEQ] = b1; C2[idx + NSEQ] = b2;  // e = gcol+1
                }
            }
        }
    }
}

// ---------------------------------------------------------------------------
// Generic batched GEMM kernel (scores / PV)
// ---------------------------------------------------------------------------
struct GemmArgs {
    const __half* A[3];
    const __half* B[3];
    long long batchA, batchB, batchC;
    int npairs, K, lda, ldb, ldc;
    float* Cf;
    __half *C1, *C2;
    const float* bias;
};

template <int MODE, int BNT>
__global__ __launch_bounds__(NTHREADS)
void gemm_kernel(GemmArgs ga)
{
    extern __shared__ __align__(16) char smem[];
    gemm_core<MODE, BNT>(ga.A, ga.B, ga.batchA, ga.batchB, ga.batchC,
                         ga.npairs, ga.K, ga.lda, ga.ldb, ga.ldc,
                         ga.Cf, ga.C1, ga.C2, ga.bias,
                         blockIdx.x, blockIdx.y, blockIdx.z, smem);
}

// ---------------------------------------------------------------------------
// Merged QKV projection: grid.z = 0(Q) / 1(K) / 2(V, transposed split out)
// ---------------------------------------------------------------------------
struct ProjArgs {
    const __half* A[3];
    const __half* Bq[3];
    const __half* Bk[3];
    const __half* Bv[3];
    const float *bq, *bk, *bv;
    __half *q1, *q2, *k1, *k2, *v1, *v2;
};

__global__ __launch_bounds__(NTHREADS)
void proj_kernel(ProjArgs pa)
{
    extern __shared__ __align__(16) char smem[];
    int z = blockIdx.z;
    if (z == 0) {
        gemm_core<2, 128>(pa.A, pa.Bq, 0, 0, 0, 3, DIM, DIM, DIM, DIM,
                          nullptr, pa.q1, pa.q2, pa.bq,
                          blockIdx.x, blockIdx.y, 0, smem);
    } else if (z == 1) {
        gemm_core<2, 128>(pa.A, pa.Bk, 0, 0, 0, 3, DIM, DIM, DIM, DIM,
                          nullptr, pa.k1, pa.k2, pa.bk,
                          blockIdx.x, blockIdx.y, 0, smem);
    } else {
        gemm_core<3, 128>(pa.A, pa.Bv, 0, 0, 0, 3, DIM, DIM, DIM, DIM,
                          nullptr, pa.v1, pa.v2, pa.bv,
                          blockIdx.x, blockIdx.y, 0, smem);
    }
}

#define SMEM_128 (NSTAGE * (A_SM + 128 * ROWB))  // 110592
#define SMEM_64  (NSTAGE * (A_SM + 64 * ROWB))   // 82944

// ---------------------------------------------------------------------------
extern "C" void kernel_launch(void* const* d_in, const int* in_sizes, int n_in,
                              void* d_out, int out_size)
{
    const float* x  = (const float*)d_in[0];
    const float* Wq = (const float*)d_in[1];
    const float* bq = (const float*)d_in[2];
    const float* Wk = (const float*)d_in[3];
    const float* bk = (const float*)d_in[4];
    const float* Wv = (const float*)d_in[5];
    const float* bv = (const float*)d_in[6];
    float* out = (float*)d_out;

    void* p;
    cudaGetSymbolAddress(&p, g_xh);  __half* xh = (__half*)p;
    cudaGetSymbolAddress(&p, g_wqh); __half* wqh = (__half*)p;
    cudaGetSymbolAddress(&p, g_wkh); __half* wkh = (__half*)p;
    cudaGetSymbolAddress(&p, g_wvh); __half* wvh = (__half*)p;
    cudaGetSymbolAddress(&p, g_qh);  __half* qh = (__half*)p;
    cudaGetSymbolAddress(&p, g_kh);  __half* kh = (__half*)p;
    cudaGetSymbolAddress(&p, g_vth); __half* vth = (__half*)p;
    cudaGetSymbolAddress(&p, g_s);   float* sptr = (float*)p;
    cudaGetSymbolAddress(&p, g_ph);  __half* ph = (__half*)p;

    static bool attr_done = false;
    if (!attr_done) {
        cudaFuncSetAttribute((const void*)gemm_kernel<0, 128>,
                             cudaFuncAttributeMaxDynamicSharedMemorySize, SMEM_128);
        cudaFuncSetAttribute((const void*)gemm_kernel<0, 64>,
                             cudaFuncAttributeMaxDynamicSharedMemorySize, SMEM_64);
        cudaFuncSetAttribute((const void*)proj_kernel,
                             cudaFuncAttributeMaxDynamicSharedMemorySize, SMEM_128);
        attr_done = true;
    }

    // 1) 2-way fp16 splits: x (one launch) + 3 weights (one merged launch)
    split2_kernel<<<(XSZ / 4 + 255) / 256, 256>>>(x, xh, xh + XSZ, XSZ / 4);
    wsplit2_kernel<<<dim3((WSZ / 4 + 255) / 256, 3), 256>>>(
        Wq, Wk, Wv,
        wqh, wqh + WSZ, wkh, wkh + WSZ, wvh, wvh + WSZ, WSZ / 4);

    const int Pa[3] = {0, 0, 1}, Pb[3] = {0, 1, 0};  // hi*hi, hi*lo, lo*hi

    // 2) merged Q/K/V projections (V writes transposed split directly)
    {
        ProjArgs pa = {};
        for (int i = 0; i < 3; i++) {
            pa.A[i]  = xh  + (size_t)Pa[i] * XSZ;
            pa.Bq[i] = wqh + (size_t)Pb[i] * WSZ;
            pa.Bk[i] = wkh + (size_t)Pb[i] * WSZ;
            pa.Bv[i] = wvh + (size_t)Pb[i] * WSZ;
        }
        pa.bq = bq; pa.bk = bk; pa.bv = bv;
        pa.q1 = qh; pa.q2 = qh + XSZ;
        pa.k1 = kh; pa.k2 = kh + XSZ;
        pa.v1 = vth; pa.v2 = vth + (size_t)BATCH * DIM * NSEQ;
        proj_kernel<<<dim3(DIM / 128, ROWS / BM, 3), NTHREADS, SMEM_128>>>(pa);
    }

    // 3) scores S = Q K^T (3 pairs, fp32)
    {
        GemmArgs ga = {};
        for (int i = 0; i < 3; i++) { ga.A[i] = qh + (size_t)Pa[i] * XSZ; ga.B[i] = kh + (size_t)Pb[i] * XSZ; }
        ga.batchA = ga.batchB = (long long)NSEQ * DIM;
        ga.batchC = (long long)NSEQ * NSEQ;
        ga.npairs = 3; ga.K = DIM; ga.lda = DIM; ga.ldb = DIM; ga.ldc = NSEQ;
        ga.Cf = sptr; ga.bias = nullptr;
        gemm_kernel<0, 128><<<dim3(NSEQ / 128, NSEQ / BM, BATCH), NTHREADS, SMEM_128>>>(ga);
    }
    // 4) softmax -> 2-split fp16 P
    softmax_kernel<<<BATCH * NSEQ, 256>>>();

    // 5) O = P V (3 pairs, fp32, BN=64 to fill the machine: 1024 CTAs)
    {
        GemmArgs ga = {};
        for (int i = 0; i < 3; i++) {
            ga.A[i] = ph + (size_t)Pa[i] * (size_t)SSZ;
            ga.B[i] = vth + (size_t)Pb[i] * ((size_t)BATCH * DIM * NSEQ);
        }
        ga.batchA = (long long)NSEQ * NSEQ;
        ga.batchB = (long long)DIM * NSEQ;
        ga.batchC = (long long)NSEQ * DIM;
        ga.npairs = 3; ga.K = NSEQ; ga.lda = NSEQ; ga.ldb = NSEQ; ga.ldc = DIM;
        ga.Cf = out; ga.bias = nullptr;
        gemm_kernel<0, 64><<<dim3(DIM / 64, NSEQ / BM, BATCH), NTHREADS, SMEM_64>>>(ga);
    }
}

// round 17
// speedup vs baseline: 1.0394x; 1.0394x over previous
#include <cuda_runtime.h>
#include <cuda_fp16.h>
#include <cstdint>

#define BATCH 8
#define NSEQ  2048
#define DIM   512
#define ROWS  (BATCH * NSEQ)   // 16384

// ---- mma.sync GEMM tiling ----
#define BM 128
#define BN 128
#define BK 64
#define NTHREADS 256
#define ROWB 144                        // smem row stride (bytes): 128+16, conflict-free
#define A_SM (BM * ROWB)                // 18432
#define B_SM (BN * ROWB)                // 18432
#define STAGE_SM (A_SM + B_SM)          // 36864
#define NSTAGE 3
#define SMEM_TOTAL (NSTAGE * STAGE_SM)  // 110592 (2 CTAs/SM)

#define XSZ (ROWS * DIM)
#define WSZ (DIM * DIM)
#define SSZ ((size_t)BATCH * NSEQ * NSEQ)

// ---------------------------------------------------------------------------
// Scratch (allocation-free rule: __device__ globals)
// ---------------------------------------------------------------------------
__device__ __half g_xh[2][XSZ];
__device__ __half g_wqh[2][WSZ];
__device__ __half g_wkh[2][WSZ];
__device__ __half g_wvh[2][WSZ];
__device__ __half g_qh[2][XSZ];
__device__ __half g_kh[2][XSZ];
__device__ __half g_vth[2][(size_t)BATCH * DIM * NSEQ];
__device__ float  g_s[SSZ];
__device__ __half g_ph[2][SSZ];

// ---------------------------------------------------------------------------
// PTX helpers
// ---------------------------------------------------------------------------
static __device__ __forceinline__ uint32_t smem_u32(const void* p) {
    uint32_t a;
    asm("{ .reg .u64 t; cvta.to.shared.u64 t, %1; cvt.u32.u64 %0, t; }" : "=r"(a) : "l"(p));
    return a;
}
static __device__ __forceinline__ void cp16(uint32_t saddr, const void* g) {
    asm volatile("cp.async.cg.shared.global [%0], [%1], 16;" :: "r"(saddr), "l"(g));
}
static __device__ __forceinline__ void cp_commit() {
    asm volatile("cp.async.commit_group;" ::: "memory");
}
static __device__ __forceinline__ void cp_wait0() {
    asm volatile("cp.async.wait_group 0;" ::: "memory");
}
static __device__ __forceinline__ void cp_wait1() {
    asm volatile("cp.async.wait_group 1;" ::: "memory");
}
#define LDSM4(R0, R1, R2, R3, addr) \
    asm volatile("ldmatrix.sync.aligned.m8n8.x4.shared.b16 {%0,%1,%2,%3}, [%4];" \
                 : "=r"(R0), "=r"(R1), "=r"(R2), "=r"(R3) : "r"(addr))
#define MMA16816(c0, c1, c2, c3, a0, a1, a2, a3, b0, b1) \
    asm volatile("mma.sync.aligned.m16n8k16.row.col.f32.f16.f16.f32 " \
                 "{%0,%1,%2,%3}, {%4,%5,%6,%7}, {%8,%9}, {%0,%1,%2,%3};" \
                 : "+f"(c0), "+f"(c1), "+f"(c2), "+f"(c3) \
                 : "r"(a0), "r"(a1), "r"(a2), "r"(a3), "r"(b0), "r"(b1))

// ---------------------------------------------------------------------------
// Elementwise 2-way fp16 splits
// ---------------------------------------------------------------------------
static __device__ __forceinline__ void split2_body(const float* in, __half* o1,
                                                   __half* o2, int i)
{
    float4 v = ((const float4*)in)[i];
    float val[4] = {v.x, v.y, v.z, v.w};
    __half h1[4], h2[4];
#pragma unroll
    for (int j = 0; j < 4; j++) {
        h1[j] = __float2half_rn(val[j]);
        h2[j] = __float2half_rn(val[j] - __half2float(h1[j]));
    }
    ((__half2*)o1)[2 * i]     = __halves2half2(h1[0], h1[1]);
    ((__half2*)o1)[2 * i + 1] = __halves2half2(h1[2], h1[3]);
    ((__half2*)o2)[2 * i]     = __halves2half2(h2[0], h2[1]);
    ((__half2*)o2)[2 * i + 1] = __halves2half2(h2[2], h2[3]);
}

__global__ void split2_kernel(const float* __restrict__ in,
                              __half* __restrict__ o1,
                              __half* __restrict__ o2, int n4)
{
    int i = blockIdx.x * blockDim.x + threadIdx.x;
    if (i < n4) split2_body(in, o1, o2, i);
}

__global__ void wsplit2_kernel(const float* __restrict__ Wq,
                               const float* __restrict__ Wk,
                               const float* __restrict__ Wv,
                               __half* __restrict__ q1, __half* __restrict__ q2,
                               __half* __restrict__ k1, __half* __restrict__ k2,
                               __half* __restrict__ v1, __half* __restrict__ v2,
                               int n4)
{
    int i = blockIdx.x * blockDim.x + threadIdx.x;
    if (i >= n4) return;
    if (blockIdx.y == 0)      split2_body(Wq, q1, q2, i);
    else if (blockIdx.y == 1) split2_body(Wk, k1, k2, i);
    else                      split2_body(Wv, v1, v2, i);
}

// ---------------------------------------------------------------------------
// Softmax over rows of S; writes 2-way fp16 split P
// ---------------------------------------------------------------------------
__global__ __launch_bounds__(256) void softmax_kernel()
{
    __shared__ float red[8];
    const float* S = g_s + (size_t)blockIdx.x * NSEQ;
    const int tid = threadIdx.x, lane = tid & 31, wid = tid >> 5;

    float4 v0 = *(const float4*)(S + tid * 8);
    float4 v1 = *(const float4*)(S + tid * 8 + 4);
    float e[8] = {v0.x, v0.y, v0.z, v0.w, v1.x, v1.y, v1.z, v1.w};

    float m = e[0];
#pragma unroll
    for (int i = 1; i < 8; i++) m = fmaxf(m, e[i]);
#pragma unroll
    for (int off = 16; off > 0; off >>= 1) m = fmaxf(m, __shfl_xor_sync(~0u, m, off));
    if (lane == 0) red[wid] = m;
    __syncthreads();
    float bm = red[0];
#pragma unroll
    for (int i = 1; i < 8; i++) bm = fmaxf(bm, red[i]);
    __syncthreads();

    float s = 0.f;
#pragma unroll
    for (int i = 0; i < 8; i++) { e[i] = __expf(e[i] - bm); s += e[i]; }
#pragma unroll
    for (int off = 16; off > 0; off >>= 1) s += __shfl_xor_sync(~0u, s, off);
    if (lane == 0) red[wid] = s;
    __syncthreads();
    float bs = 0.f;
#pragma unroll
    for (int i = 0; i < 8; i++) bs += red[i];
    float inv = 1.0f / bs;

    size_t base = (size_t)blockIdx.x * NSEQ + tid * 8;
    __half h1[8], h2[8];
#pragma unroll
    for (int i = 0; i < 8; i++) {
        float p = e[i] * inv;
        h1[i] = __float2half_rn(p);
        h2[i] = __float2half_rn(p - __half2float(h1[i]));
    }
#pragma unroll
    for (int i = 0; i < 4; i++) {
        ((__half2*)(g_ph[0] + base))[i] = __halves2half2(h1[2 * i], h1[2 * i + 1]);
        ((__half2*)(g_ph[1] + base))[i] = __halves2half2(h2[2 * i], h2[2 * i + 1]);
    }
}

// ---------------------------------------------------------------------------
// GEMM core: C[m,n] = sum_p sum_k A_p[m,k]*B_p[n,k] (+bias[n])
// MODE 0: fp32 out.  MODE 2: 2-way fp16 split out (row-major).
// MODE 3: 2-way fp16 split out, TRANSPOSED to [b][e][m] (for V).
// 256 threads; warp grid 2(m) x 4(n); warp tile 64x32; BK=64; 3-stage cp.async.
// ---------------------------------------------------------------------------
template <int MODE>
static __device__ __forceinline__ void gemm_core(
    const __half* const* Aps, const __half* const* Bps,
    long long batchA, long long batchB, long long batchC,
    int npairs, int K, int lda, int ldb, int ldc,
    float* Cf, __half* C1, __half* C2, const float* bias,
    int nt, int mt, int bz, char* smem)
{
    constexpr int NJ = 4;                // n8-tiles per warp (32 cols)

    const int tid  = threadIdx.x;
    const int wid  = tid >> 5;
    const int lane = tid & 31;

    const int m_base = (wid & 1) * 64;
    const int n_base = (wid >> 1) * 32;

    const uint32_t s0 = smem_u32(smem);

    const int KCH = K / BK;
    const int NIT = npairs * KCH;

    float acc[4][NJ][4];
#pragma unroll
    for (int i = 0; i < 4; i++)
#pragma unroll
        for (int j = 0; j < NJ; j++)
#pragma unroll
            for (int r = 0; r < 4; r++) acc[i][j][r] = 0.f;

    const int lrow0 = tid >> 3;          // 0..31
    const int lc16  = tid & 7;           // 16B chunk within 128B row

    auto load_stage = [&](int it, int s) {
        int p = it / KCH, k0 = (it % KCH) * BK;
        const __half* Ab = Aps[p] + (size_t)bz * batchA + k0;
        const __half* Bb = Bps[p] + (size_t)bz * batchB + k0;
        uint32_t dA = s0 + s * STAGE_SM;
        uint32_t dB = dA + A_SM;
#pragma unroll
        for (int h = 0; h < 4; h++) {    // A: 128 rows x 128B
            int r = lrow0 + h * 32;
            cp16(dA + r * ROWB + lc16 * 16,
                 Ab + (size_t)(mt * BM + r) * lda + lc16 * 8);
        }
#pragma unroll
        for (int h = 0; h < 4; h++) {    // B: 128 rows x 128B
            int r = lrow0 + h * 32;
            cp16(dB + r * ROWB + lc16 * 16,
                 Bb + (size_t)(nt * BN + r) * ldb + lc16 * 8);
        }
        cp_commit();
    };

    load_stage(0, 0);
    if (NIT > 1) load_stage(1, 1);

    int st = 0;
    for (int it = 0; it < NIT; it++) {
        if (it + 1 < NIT) cp_wait1(); else cp_wait0();
        __syncthreads();
        if (it + 2 < NIT) {
            int s2 = st + 2; if (s2 >= NSTAGE) s2 -= NSTAGE;
            load_stage(it + 2, s2);
        }

        uint32_t bA = s0 + st * STAGE_SM;
        uint32_t bB = bA + A_SM;
#pragma unroll
        for (int ks = 0; ks < 4; ks++) {
            uint32_t a[4][4];
#pragma unroll
            for (int mi = 0; mi < 4; mi++) {
                int row = m_base + mi * 16 + (lane & 15);
                int kc  = ks * 16 + (lane >> 4) * 8;
                LDSM4(a[mi][0], a[mi][1], a[mi][2], a[mi][3],
                      bA + row * ROWB + kc * 2);
            }
            uint32_t b[NJ][2];
#pragma unroll
            for (int j2 = 0; j2 < NJ / 2; j2++) {
                int grp = lane >> 3;
                int row = n_base + j2 * 16 + ((grp >> 1) * 8) + (lane & 7);
                int kc  = ks * 16 + (grp & 1) * 8;
                uint32_t r0, r1, r2, r3;
                LDSM4(r0, r1, r2, r3, bB + row * ROWB + kc * 2);
                b[2 * j2][0] = r0; b[2 * j2][1] = r1;
                b[2 * j2 + 1][0] = r2; b[2 * j2 + 1][1] = r3;
            }
#pragma unroll
            for (int mi = 0; mi < 4; mi++)
#pragma unroll
                for (int nj = 0; nj < NJ; nj++)
                    MMA16816(acc[mi][nj][0], acc[mi][nj][1], acc[mi][nj][2], acc[mi][nj][3],
                             a[mi][0], a[mi][1], a[mi][2], a[mi][3],
                             b[nj][0], b[nj][1]);
        }
        if (++st >= NSTAGE) st = 0;
    }

    const int r0l = lane >> 2;
    const int c0l = (lane & 3) * 2;
#pragma unroll
    for (int mi = 0; mi < 4; mi++) {
#pragma unroll
        for (int half = 0; half < 2; half++) {
            int grow = mt * BM + m_base + mi * 16 + r0l + half * 8;
#pragma unroll
            for (int nj = 0; nj < NJ; nj++) {
                int gcol = nt * BN + n_base + nj * 8 + c0l;
                float v0 = acc[mi][nj][2 * half];
                float v1 = acc[mi][nj][2 * half + 1];
                if (bias) { v0 += bias[gcol]; v1 += bias[gcol + 1]; }
                if (MODE == 0) {
                    float* C = Cf + (size_t)bz * batchC + (size_t)grow * ldc + gcol;
                    *(float2*)C = make_float2(v0, v1);
                } else if (MODE == 2) {
                    size_t off = (size_t)grow * ldc + gcol;
                    __half a1 = __float2half_rn(v0);
                    __half a2 = __float2half_rn(v0 - __half2float(a1));
                    __half b1 = __float2half_rn(v1);
                    __half b2 = __float2half_rn(v1 - __half2float(b1));
                    *(__half2*)(C1 + off) = __halves2half2(a1, b1);
                    *(__half2*)(C2 + off) = __halves2half2(a2, b2);
                } else {
                    // transposed: vth[b][e][m]; b = grow/NSEQ, m = grow%NSEQ, e = gcol
                    size_t idx = ((size_t)(grow >> 11) * DIM + gcol) * NSEQ + (grow & (NSEQ - 1));
                    __half a1 = __float2half_rn(v0);
                    __half a2 = __float2half_rn(v0 - __half2float(a1));
                    __half b1 = __float2half_rn(v1);
                    __half b2 = __float2half_rn(v1 - __half2float(b1));
                    C1[idx] = a1;        C2[idx] = a2;         // e = gcol
                    C1[idx + NSEQ] = b1; C2[idx + NSEQ] = b2;  // e = gcol+1
                }
            }
        }
    }
}

// ---------------------------------------------------------------------------
// Generic batched GEMM kernel (scores / PV)
// ---------------------------------------------------------------------------
struct GemmArgs {
    const __half* A[3];
    const __half* B[3];
    long long batchA, batchB, batchC;
    int npairs, K, lda, ldb, ldc;
    float* Cf;
    __half *C1, *C2;
    const float* bias;
};

template <int MODE>
__global__ __launch_bounds__(NTHREADS, 2)
void gemm_kernel(GemmArgs ga)
{
    extern __shared__ __align__(16) char smem[];
    gemm_core<MODE>(ga.A, ga.B, ga.batchA, ga.batchB, ga.batchC,
                    ga.npairs, ga.K, ga.lda, ga.ldb, ga.ldc,
                    ga.Cf, ga.C1, ga.C2, ga.bias,
                    blockIdx.x, blockIdx.y, blockIdx.z, smem);
}

// ---------------------------------------------------------------------------
// Merged QKV projection: grid.z = 0(Q) / 1(K) / 2(V, transposed split out)
// ---------------------------------------------------------------------------
struct ProjArgs {
    const __half* A[3];
    const __half* Bq[3];
    const __half* Bk[3];
    const __half* Bv[3];
    const float *bq, *bk, *bv;
    __half *q1, *q2, *k1, *k2, *v1, *v2;
};

__global__ __launch_bounds__(NTHREADS, 2)
void proj_kernel(ProjArgs pa)
{
    extern __shared__ __align__(16) char smem[];
    int z = blockIdx.z;
    if (z == 0) {
        gemm_core<2>(pa.A, pa.Bq, 0, 0, 0, 3, DIM, DIM, DIM, DIM,
                     nullptr, pa.q1, pa.q2, pa.bq,
                     blockIdx.x, blockIdx.y, 0, smem);
    } else if (z == 1) {
        gemm_core<2>(pa.A, pa.Bk, 0, 0, 0, 3, DIM, DIM, DIM, DIM,
                     nullptr, pa.k1, pa.k2, pa.bk,
                     blockIdx.x, blockIdx.y, 0, smem);
    } else {
        gemm_core<3>(pa.A, pa.Bv, 0, 0, 0, 3, DIM, DIM, DIM, DIM,
                     nullptr, pa.v1, pa.v2, pa.bv,
                     blockIdx.x, blockIdx.y, 0, smem);
    }
}

// ---------------------------------------------------------------------------
extern "C" void kernel_launch(void* const* d_in, const int* in_sizes, int n_in,
                              void* d_out, int out_size)
{
    const float* x  = (const float*)d_in[0];
    const float* Wq = (const float*)d_in[1];
    const float* bq = (const float*)d_in[2];
    const float* Wk = (const float*)d_in[3];
    const float* bk = (const float*)d_in[4];
    const float* Wv = (const float*)d_in[5];
    const float* bv = (const float*)d_in[6];
    float* out = (float*)d_out;

    void* p;
    cudaGetSymbolAddress(&p, g_xh);  __half* xh = (__half*)p;
    cudaGetSymbolAddress(&p, g_wqh); __half* wqh = (__half*)p;
    cudaGetSymbolAddress(&p, g_wkh); __half* wkh = (__half*)p;
    cudaGetSymbolAddress(&p, g_wvh); __half* wvh = (__half*)p;
    cudaGetSymbolAddress(&p, g_qh);  __half* qh = (__half*)p;
    cudaGetSymbolAddress(&p, g_kh);  __half* kh = (__half*)p;
    cudaGetSymbolAddress(&p, g_vth); __half* vth = (__half*)p;
    cudaGetSymbolAddress(&p, g_s);   float* sptr = (float*)p;
    cudaGetSymbolAddress(&p, g_ph);  __half* ph = (__half*)p;

    static bool attr_done = false;
    if (!attr_done) {
        cudaFuncSetAttribute((const void*)gemm_kernel<0>,
                             cudaFuncAttributeMaxDynamicSharedMemorySize, SMEM_TOTAL);
        cudaFuncSetAttribute((const void*)proj_kernel,
                             cudaFuncAttributeMaxDynamicSharedMemorySize, SMEM_TOTAL);
        attr_done = true;
    }

    // 1) 2-way fp16 splits: x (one launch) + 3 weights (one merged launch)
    split2_kernel<<<(XSZ / 4 + 255) / 256, 256>>>(x, xh, xh + XSZ, XSZ / 4);
    wsplit2_kernel<<<dim3((WSZ / 4 + 255) / 256, 3), 256>>>(
        Wq, Wk, Wv,
        wqh, wqh + WSZ, wkh, wkh + WSZ, wvh, wvh + WSZ, WSZ / 4);

    const int Pa[3] = {0, 0, 1}, Pb[3] = {0, 1, 0};  // hi*hi, hi*lo, lo*hi

    // 2) merged Q/K/V projections (V writes transposed split directly)
    {
        ProjArgs pa = {};
        for (int i = 0; i < 3; i++) {
            pa.A[i]  = xh  + (size_t)Pa[i] * XSZ;
            pa.Bq[i] = wqh + (size_t)Pb[i] * WSZ;
            pa.Bk[i] = wkh + (size_t)Pb[i] * WSZ;
            pa.Bv[i] = wvh + (size_t)Pb[i] * WSZ;
        }
        pa.bq = bq; pa.bk = bk; pa.bv = bv;
        pa.q1 = qh; pa.q2 = qh + XSZ;
        pa.k1 = kh; pa.k2 = kh + XSZ;
        pa.v1 = vth; pa.v2 = vth + (size_t)BATCH * DIM * NSEQ;
        proj_kernel<<<dim3(DIM / BN, ROWS / BM, 3), NTHREADS, SMEM_TOTAL>>>(pa);
    }

    // 3) scores S = Q K^T (3 pairs, fp32)
    {
        GemmArgs ga = {};
        for (int i = 0; i < 3; i++) { ga.A[i] = qh + (size_t)Pa[i] * XSZ; ga.B[i] = kh + (size_t)Pb[i] * XSZ; }
        ga.batchA = ga.batchB = (long long)NSEQ * DIM;
        ga.batchC = (long long)NSEQ * NSEQ;
        ga.npairs = 3; ga.K = DIM; ga.lda = DIM; ga.ldb = DIM; ga.ldc = NSEQ;
        ga.Cf = sptr; ga.bias = nullptr;
        gemm_kernel<0><<<dim3(NSEQ / BN, NSEQ / BM, BATCH), NTHREADS, SMEM_TOTAL>>>(ga);
    }
    // 4) softmax -> 2-split fp16 P
    softmax_kernel<<<BATCH * NSEQ, 256>>>();

    // 5) O = P V (3 pairs, fp32)
    {
        GemmArgs ga = {};
        for (int i = 0; i < 3; i++) {
            ga.A[i] = ph + (size_t)Pa[i] * (size_t)SSZ;
            ga.B[i] = vth + (size_t)Pb[i] * ((size_t)BATCH * DIM * NSEQ);
        }
        ga.batchA = (long long)NSEQ * NSEQ;
        ga.batchB = (long long)DIM * NSEQ;
        ga.batchC = (long long)NSEQ * DIM;
        ga.npairs = 3; ga.K = NSEQ; ga.lda = NSEQ; ga.ldb = NSEQ; ga.ldc = DIM;
        ga.Cf = out; ga.bias = nullptr;
        gemm_kernel<0><<<dim3(DIM / BN, NSEQ / BM, BATCH), NTHREADS, SMEM_TOTAL>>>(ga);
    }
}